// round 2
// baseline (speedup 1.0000x reference)
#include <cuda_runtime.h>
#include <cuda_bf16.h>

// Problem constants
#define NN 100000
#define EE 1600000
#define DD 128

// ---------------- device scratch (no allocations allowed) ----------------
__device__ int   g_is64;
__device__ int   g_deg[NN];
__device__ int   g_rowptr[NN + 1];
__device__ int   g_cursor[NN];
__device__ int   g_col[EE];
__device__ float g_wgt[EE];
__device__ float g_dinv[NN];
__device__ float g_bufA[NN * DD];   // aggregation output
__device__ float g_bufB[NN * DD];   // layer-1 activation

// ---------------- helpers ----------------
__device__ __forceinline__ int load_idx(const void* ei, int pos, int is64) {
    if (is64) return (int)((const long long*)ei)[pos];
    return ((const int*)ei)[pos];
}

// ---------------- kernels ----------------

// Detect whether edge_index is int64 or int32 by inspecting odd int32 words.
// int64 values < 2^31 have zero hi-words at every odd int32 position.
__global__ void k_detect(const int* __restrict__ ei32) {
    int zeros = 0;
#pragma unroll
    for (int i = 0; i < 64; i++)
        if (ei32[2 * i + 1] == 0) zeros++;
    g_is64 = (zeros >= 60) ? 1 : 0;
}

__global__ void k_zero() {
    int i = blockIdx.x * blockDim.x + threadIdx.x;
    if (i < NN) { g_deg[i] = 0; g_cursor[i] = 0; }
}

__global__ void k_count(const void* __restrict__ ei, int E) {
    int i = blockIdx.x * blockDim.x + threadIdx.x;
    if (i >= E) return;
    int d = load_idx(ei, E + i, g_is64);
    if ((unsigned)d < (unsigned)NN) atomicAdd(&g_deg[d], 1);
}

__global__ void k_dinv() {
    int i = blockIdx.x * blockDim.x + threadIdx.x;
    if (i < NN) g_dinv[i] = rsqrtf((float)g_deg[i] + 1.0f);
}

// single-block scan over g_deg -> g_rowptr (rowptr[0]=0, rowptr[i+1]=sum deg[0..i])
__global__ void k_scan(int n) {
    __shared__ int sh[1024];
    __shared__ int carry;
    int t = threadIdx.x;
    if (t == 0) { carry = 0; g_rowptr[0] = 0; }
    __syncthreads();
    for (int base = 0; base < n; base += 1024) {
        int v = (base + t < n) ? g_deg[base + t] : 0;
        sh[t] = v;
        __syncthreads();
        for (int off = 1; off < 1024; off <<= 1) {
            int add = (t >= off) ? sh[t - off] : 0;
            __syncthreads();
            sh[t] += add;
            __syncthreads();
        }
        if (base + t < n) g_rowptr[base + t + 1] = carry + sh[t];
        __syncthreads();
        if (t == 0) carry += sh[1023];
        __syncthreads();
    }
}

__global__ void k_scatter(const void* __restrict__ ei, int E) {
    int i = blockIdx.x * blockDim.x + threadIdx.x;
    if (i >= E) return;
    int is64 = g_is64;
    int s = load_idx(ei, i, is64);
    int d = load_idx(ei, E + i, is64);
    if ((unsigned)s >= (unsigned)NN || (unsigned)d >= (unsigned)NN) return;
    int pos = atomicAdd(&g_cursor[d], 1);
    int idx = g_rowptr[d] + pos;
    g_col[idx] = s;
    g_wgt[idx] = g_dinv[s] * g_dinv[d];
}

// warp-per-node aggregation: out[i] = sum_{j in row i} w_j * x[col_j] + dinv_i^2 * x[i]
__global__ void k_agg(const float4* __restrict__ x, float4* __restrict__ out) {
    int gw = (blockIdx.x * blockDim.x + threadIdx.x) >> 5;
    int lane = threadIdx.x & 31;
    if (gw >= NN) return;
    int s = g_rowptr[gw];
    int e = g_rowptr[gw + 1];
    float di = g_dinv[gw];
    float sw = di * di;
    float4 acc = x[gw * 32 + lane];
    acc.x *= sw; acc.y *= sw; acc.z *= sw; acc.w *= sw;
    int j = s;
    for (; j + 1 < e; j += 2) {
        int c0 = g_col[j],     c1 = g_col[j + 1];
        float w0 = g_wgt[j],   w1 = g_wgt[j + 1];
        float4 v0 = x[c0 * 32 + lane];
        float4 v1 = x[c1 * 32 + lane];
        acc.x += v0.x * w0 + v1.x * w1;
        acc.y += v0.y * w0 + v1.y * w1;
        acc.z += v0.z * w0 + v1.z * w1;
        acc.w += v0.w * w0 + v1.w * w1;
    }
    if (j < e) {
        int c0 = g_col[j];
        float w0 = g_wgt[j];
        float4 v0 = x[c0 * 32 + lane];
        acc.x += v0.x * w0;
        acc.y += v0.y * w0;
        acc.z += v0.z * w0;
        acc.w += v0.w * w0;
    }
    out[gw * 32 + lane] = acc;
}

// GEMM: out[n,128] = A[n,128] @ W[128,128] + bias, epilogue ReLU or LayerNorm.
// Block: 256 threads, 64-row tile. Thread (tx=tid&31, ty=tid>>5) computes
// rows {ty + 8*i, i<8}, cols [4*tx, 4*tx+4). Each row's 128 cols live in warp ty.
template <bool LN>
__global__ void k_gemm(const float* __restrict__ A, const float* __restrict__ Wm,
                       const float* __restrict__ bias, const float* __restrict__ gamma,
                       const float* __restrict__ beta, float* __restrict__ out, int n) {
    extern __shared__ float smem[];
    float* sW = smem;            // 128*128 floats
    float* sA = smem + 16384;    // 64*128 floats
    int tid = threadIdx.x;

    const float4* W4 = (const float4*)Wm;
    float4* sW4 = (float4*)sW;
#pragma unroll
    for (int i = 0; i < 16; i++) sW4[tid + 256 * i] = W4[tid + 256 * i];

    int row0 = blockIdx.x * 64;
    const float4* A4 = (const float4*)A;
    float4* sA4 = (float4*)sA;
#pragma unroll
    for (int i = 0; i < 8; i++) {
        int idx = tid + 256 * i;
        int r = idx >> 5;
        sA4[idx] = (row0 + r < n) ? A4[(row0 + r) * 32 + (idx & 31)]
                                  : make_float4(0.f, 0.f, 0.f, 0.f);
    }
    __syncthreads();

    int tx = tid & 31, ty = tid >> 5;
    float4 acc[8];
#pragma unroll
    for (int i = 0; i < 8; i++) acc[i] = make_float4(0.f, 0.f, 0.f, 0.f);

    const float* a0 = sA + ty * 128;
#pragma unroll 4
    for (int k = 0; k < 128; k++) {
        float4 wv = sW4[k * 32 + tx];
#pragma unroll
        for (int i = 0; i < 8; i++) {
            float a = a0[i * 8 * 128 + k];
            acc[i].x += a * wv.x;
            acc[i].y += a * wv.y;
            acc[i].z += a * wv.z;
            acc[i].w += a * wv.w;
        }
    }

    float4 bv = ((const float4*)bias)[tx];
    if (!LN) {
#pragma unroll
        for (int i = 0; i < 8; i++) {
            int r = row0 + ty + 8 * i;
            if (r < n) {
                float4 o;
                o.x = fmaxf(acc[i].x + bv.x, 0.f);
                o.y = fmaxf(acc[i].y + bv.y, 0.f);
                o.z = fmaxf(acc[i].z + bv.z, 0.f);
                o.w = fmaxf(acc[i].w + bv.w, 0.f);
                ((float4*)out)[r * 32 + tx] = o;
            }
        }
    } else {
        float4 gv = ((const float4*)gamma)[tx];
        float4 btv = ((const float4*)beta)[tx];
#pragma unroll
        for (int i = 0; i < 8; i++) {
            int r = row0 + ty + 8 * i;
            float4 v;
            v.x = acc[i].x + bv.x;
            v.y = acc[i].y + bv.y;
            v.z = acc[i].z + bv.z;
            v.w = acc[i].w + bv.w;
            float sum = v.x + v.y + v.z + v.w;
#pragma unroll
            for (int off = 16; off > 0; off >>= 1)
                sum += __shfl_xor_sync(0xFFFFFFFFu, sum, off);
            float mu = sum * (1.0f / 128.0f);
            float dx = v.x - mu, dy = v.y - mu, dz = v.z - mu, dw = v.w - mu;
            float sq = dx * dx + dy * dy + dz * dz + dw * dw;
#pragma unroll
            for (int off = 16; off > 0; off >>= 1)
                sq += __shfl_xor_sync(0xFFFFFFFFu, sq, off);
            float rstd = rsqrtf(sq * (1.0f / 128.0f) + 1e-5f);
            if (r < n) {
                float4 o;
                o.x = dx * rstd * gv.x + btv.x;
                o.y = dy * rstd * gv.y + btv.y;
                o.z = dz * rstd * gv.z + btv.z;
                o.w = dw * rstd * gv.w + btv.w;
                ((float4*)out)[r * 32 + tx] = o;
            }
        }
    }
}

// ---------------- launch ----------------
extern "C" void kernel_launch(void* const* d_in, const int* in_sizes, int n_in,
                              void* d_out, int out_size) {
    const float* x   = (const float*)d_in[0];
    const void*  ei  = d_in[1];
    const float* W1  = (const float*)d_in[2];
    const float* b1  = (const float*)d_in[3];
    const float* W2  = (const float*)d_in[4];
    const float* b2  = (const float*)d_in[5];
    const float* gm  = (const float*)d_in[6];
    const float* bt  = (const float*)d_in[7];
    float*       out = (float*)d_out;

    int E = in_sizes[1] / 2;

    float* bufA; cudaGetSymbolAddress((void**)&bufA, g_bufA);
    float* bufB; cudaGetSymbolAddress((void**)&bufB, g_bufB);

    const size_t smem_gemm = (128 * 128 + 64 * 128) * sizeof(float);  // 96 KB
    cudaFuncSetAttribute(k_gemm<false>, cudaFuncAttributeMaxDynamicSharedMemorySize,
                         (int)smem_gemm);
    cudaFuncSetAttribute(k_gemm<true>, cudaFuncAttributeMaxDynamicSharedMemorySize,
                         (int)smem_gemm);

    int ebl = (E + 255) / 256;
    int nbl = (NN + 255) / 256;

    // ---- CSR build (shared by both layers) ----
    k_detect<<<1, 1>>>((const int*)ei);
    k_zero<<<nbl, 256>>>();
    k_count<<<ebl, 256>>>(ei, E);
    k_dinv<<<nbl, 256>>>();
    k_scan<<<1, 1024>>>(NN);
    k_scatter<<<ebl, 256>>>(ei, E);

    int agg_blocks = (NN * 32 + 255) / 256;   // warp per node, 8 warps/block
    int gemm_blocks = (NN + 63) / 64;

    // ---- layer 1: agg(x) -> bufA ; relu(bufA@W1+b1) -> bufB ----
    k_agg<<<agg_blocks, 256>>>((const float4*)x, (float4*)bufA);
    k_gemm<false><<<gemm_blocks, 256, smem_gemm>>>(bufA, W1, b1, nullptr, nullptr, bufB, NN);

    // ---- layer 2: agg(bufB) -> bufA ; LN(bufA@W2+b2) -> out ----
    k_agg<<<agg_blocks, 256>>>((const float4*)bufB, (float4*)bufA);
    k_gemm<true><<<gemm_blocks, 256, smem_gemm>>>(bufA, W2, b2, gm, bt, out, NN);
}

// round 3
// speedup vs baseline: 1.3402x; 1.3402x over previous
#include <cuda_runtime.h>
#include <cuda_fp16.h>
#include <cuda_bf16.h>

// Problem constants
#define NN 100000
#define EE 1600000
#define DD 128

// ---------------- device scratch (no allocations allowed) ----------------
__device__ int    g_is64;
__device__ int    g_deg[NN];
__device__ int    g_rowptr[NN + 1];
__device__ int    g_cursor[NN];
__device__ int    g_col[EE];
__device__ float  g_wgt[EE];
__device__ float  g_dinv[NN];
__device__ __half g_h[NN * DD];     // fp16 GEMM output (g1, then reused for g2)
__device__ float  g_bufA[NN * DD];  // fp32 activation a1 (agg1 output)

// ---------------- helpers ----------------
__device__ __forceinline__ int load_idx(const void* ei, int pos, int is64) {
    if (is64) return (int)((const long long*)ei)[pos];
    return ((const int*)ei)[pos];
}

// ---------------- graph-build kernels ----------------

// Detect int64 vs int32 edge_index: int64 node ids (<2^31) have zero hi-words
// at every odd int32 position.
__global__ void k_detect(const int* __restrict__ ei32) {
    int zeros = 0;
#pragma unroll
    for (int i = 0; i < 64; i++)
        if (ei32[2 * i + 1] == 0) zeros++;
    g_is64 = (zeros >= 60) ? 1 : 0;
}

__global__ void k_zero() {
    int i = blockIdx.x * blockDim.x + threadIdx.x;
    if (i < NN) { g_deg[i] = 0; g_cursor[i] = 0; }
}

__global__ void k_count(const void* __restrict__ ei, int E) {
    int i = blockIdx.x * blockDim.x + threadIdx.x;
    if (i >= E) return;
    int d = load_idx(ei, E + i, g_is64);
    if ((unsigned)d < (unsigned)NN) atomicAdd(&g_deg[d], 1);
}

__global__ void k_dinv() {
    int i = blockIdx.x * blockDim.x + threadIdx.x;
    if (i < NN) g_dinv[i] = rsqrtf((float)g_deg[i] + 1.0f);
}

// Single-block scan via warp shuffles: g_rowptr[i+1] = sum(deg[0..i]).
__global__ void k_scan(int n) {
    __shared__ int wsum[32];
    __shared__ int carry;
    int t = threadIdx.x, lane = t & 31, w = t >> 5;
    if (t == 0) { carry = 0; g_rowptr[0] = 0; }
    __syncthreads();
    for (int base = 0; base < n; base += 1024) {
        int v = (base + t < n) ? g_deg[base + t] : 0;
        int s = v;
#pragma unroll
        for (int off = 1; off < 32; off <<= 1) {
            int u = __shfl_up_sync(0xFFFFFFFFu, s, off);
            if (lane >= off) s += u;
        }
        if (lane == 31) wsum[w] = s;
        __syncthreads();
        if (w == 0) {
            int ws = wsum[lane];
#pragma unroll
            for (int off = 1; off < 32; off <<= 1) {
                int u = __shfl_up_sync(0xFFFFFFFFu, ws, off);
                if (lane >= off) ws += u;
            }
            wsum[lane] = ws;
        }
        __syncthreads();
        int c = carry;
        int pre = (w > 0) ? wsum[w - 1] : 0;
        if (base + t < n) g_rowptr[base + t + 1] = c + pre + s;
        __syncthreads();
        if (t == 0) carry = c + wsum[31];
        __syncthreads();
    }
}

__global__ void k_scatter(const void* __restrict__ ei, int E) {
    int i = blockIdx.x * blockDim.x + threadIdx.x;
    if (i >= E) return;
    int is64 = g_is64;
    int s = load_idx(ei, i, is64);
    int d = load_idx(ei, E + i, is64);
    if ((unsigned)s >= (unsigned)NN || (unsigned)d >= (unsigned)NN) return;
    int pos = atomicAdd(&g_cursor[d], 1);
    int idx = g_rowptr[d] + pos;
    g_col[idx] = s;
    g_wgt[idx] = g_dinv[s] * g_dinv[d];
}

// ---------------- GEMM: out[n,128] = A[n,128] @ W[128,128], fp16 output ----
// Block 256 threads, 64-row tile. Thread (tx=tid&31, ty=tid>>5) computes rows
// {ty + 8*i}, cols [4*tx, 4*tx+4).
template <bool HALF_IN>
__global__ void k_gemm(const void* __restrict__ Ain, const float* __restrict__ Wm,
                       __half* __restrict__ out, int n) {
    extern __shared__ float smem[];
    float* sW = smem;            // 128*128
    float* sA = smem + 16384;    // 64*128
    int tid = threadIdx.x;

    const float4* W4 = (const float4*)Wm;
    float4* sW4 = (float4*)sW;
#pragma unroll
    for (int i = 0; i < 16; i++) sW4[tid + 256 * i] = W4[tid + 256 * i];

    int row0 = blockIdx.x * 64;
    if (!HALF_IN) {
        const float4* A4 = (const float4*)Ain;
        float4* sA4 = (float4*)sA;
#pragma unroll
        for (int i = 0; i < 8; i++) {
            int idx = tid + 256 * i;
            int r = idx >> 5;
            sA4[idx] = (row0 + r < n) ? A4[(row0 + r) * 32 + (idx & 31)]
                                      : make_float4(0.f, 0.f, 0.f, 0.f);
        }
    } else {
        const uint2* A2 = (const uint2*)Ain;  // 4 halfs per uint2
#pragma unroll
        for (int i = 0; i < 8; i++) {
            int idx = tid + 256 * i;          // uint2 index within tile (64*32)
            int r = idx >> 5;
            float4 v = make_float4(0.f, 0.f, 0.f, 0.f);
            if (row0 + r < n) {
                uint2 u = A2[(row0 + r) * 32 + (idx & 31)];
                __half2 h0 = *reinterpret_cast<__half2*>(&u.x);
                __half2 h1 = *reinterpret_cast<__half2*>(&u.y);
                float2 f0 = __half22float2(h0), f1 = __half22float2(h1);
                v = make_float4(f0.x, f0.y, f1.x, f1.y);
            }
            ((float4*)sA)[idx] = v;
        }
    }
    __syncthreads();

    int tx = tid & 31, ty = tid >> 5;
    float4 acc[8];
#pragma unroll
    for (int i = 0; i < 8; i++) acc[i] = make_float4(0.f, 0.f, 0.f, 0.f);

    const float* a0 = sA + ty * 128;
    float4* sW4r = (float4*)sW;
#pragma unroll 4
    for (int k = 0; k < 128; k++) {
        float4 wv = sW4r[k * 32 + tx];
#pragma unroll
        for (int i = 0; i < 8; i++) {
            float a = a0[i * 8 * 128 + k];
            acc[i].x += a * wv.x;
            acc[i].y += a * wv.y;
            acc[i].z += a * wv.z;
            acc[i].w += a * wv.w;
        }
    }

#pragma unroll
    for (int i = 0; i < 8; i++) {
        int r = row0 + ty + 8 * i;
        if (r < n) {
            __half2 h0 = __floats2half2_rn(acc[i].x, acc[i].y);
            __half2 h1 = __floats2half2_rn(acc[i].z, acc[i].w);
            uint2 u;
            u.x = *reinterpret_cast<unsigned*>(&h0);
            u.y = *reinterpret_cast<unsigned*>(&h1);
            ((uint2*)out)[r * 32 + tx] = u;
        }
    }
}

// ---------------- aggregation over fp16 rows ----------------
// out_row(i) = sum_j w_j * h[col_j] + dinv_i^2 * h[i]  (+bias, then ReLU or LN)
// MODE 0: +bias, ReLU, fp32 out.   MODE 1: +bias, LayerNorm, fp32 out.
template <int MODE>
__global__ void k_agg(const uint2* __restrict__ hin, float* __restrict__ out,
                      const float* __restrict__ bias, const float* __restrict__ gamma,
                      const float* __restrict__ beta) {
    int gw = (blockIdx.x * blockDim.x + threadIdx.x) >> 5;
    int lane = threadIdx.x & 31;
    if (gw >= NN) return;
    int s = g_rowptr[gw];
    int e = g_rowptr[gw + 1];
    float di = g_dinv[gw];
    float sw = di * di;

    float ax, ay, az, aw;
    {
        uint2 u = hin[gw * 32 + lane];
        __half2 h0 = *reinterpret_cast<__half2*>(&u.x);
        __half2 h1 = *reinterpret_cast<__half2*>(&u.y);
        float2 f0 = __half22float2(h0), f1 = __half22float2(h1);
        ax = f0.x * sw; ay = f0.y * sw; az = f1.x * sw; aw = f1.y * sw;
    }

    int j = s;
    for (; j + 1 < e; j += 2) {
        int c0 = g_col[j], c1 = g_col[j + 1];
        float w0 = g_wgt[j], w1 = g_wgt[j + 1];
        uint2 u0 = hin[c0 * 32 + lane];
        uint2 u1 = hin[c1 * 32 + lane];
        __half2 a0 = *reinterpret_cast<__half2*>(&u0.x);
        __half2 a1 = *reinterpret_cast<__half2*>(&u0.y);
        __half2 b0 = *reinterpret_cast<__half2*>(&u1.x);
        __half2 b1 = *reinterpret_cast<__half2*>(&u1.y);
        float2 fa0 = __half22float2(a0), fa1 = __half22float2(a1);
        float2 fb0 = __half22float2(b0), fb1 = __half22float2(b1);
        ax += fa0.x * w0 + fb0.x * w1;
        ay += fa0.y * w0 + fb0.y * w1;
        az += fa1.x * w0 + fb1.x * w1;
        aw += fa1.y * w0 + fb1.y * w1;
    }
    if (j < e) {
        int c0 = g_col[j];
        float w0 = g_wgt[j];
        uint2 u0 = hin[c0 * 32 + lane];
        __half2 a0 = *reinterpret_cast<__half2*>(&u0.x);
        __half2 a1 = *reinterpret_cast<__half2*>(&u0.y);
        float2 fa0 = __half22float2(a0), fa1 = __half22float2(a1);
        ax += fa0.x * w0;
        ay += fa0.y * w0;
        az += fa1.x * w0;
        aw += fa1.y * w0;
    }

    float4 bv = ((const float4*)bias)[lane];
    ax += bv.x; ay += bv.y; az += bv.z; aw += bv.w;

    if (MODE == 0) {
        float4 o = make_float4(fmaxf(ax, 0.f), fmaxf(ay, 0.f),
                               fmaxf(az, 0.f), fmaxf(aw, 0.f));
        ((float4*)out)[gw * 32 + lane] = o;
    } else {
        float sum = ax + ay + az + aw;
#pragma unroll
        for (int off = 16; off > 0; off >>= 1)
            sum += __shfl_xor_sync(0xFFFFFFFFu, sum, off);
        float mu = sum * (1.0f / 128.0f);
        float dx = ax - mu, dy = ay - mu, dz = az - mu, dw = aw - mu;
        float sq = dx * dx + dy * dy + dz * dz + dw * dw;
#pragma unroll
        for (int off = 16; off > 0; off >>= 1)
            sq += __shfl_xor_sync(0xFFFFFFFFu, sq, off);
        float rstd = rsqrtf(sq * (1.0f / 128.0f) + 1e-5f);
        float4 gv = ((const float4*)gamma)[lane];
        float4 btv = ((const float4*)beta)[lane];
        float4 o;
        o.x = dx * rstd * gv.x + btv.x;
        o.y = dy * rstd * gv.y + btv.y;
        o.z = dz * rstd * gv.z + btv.z;
        o.w = dw * rstd * gv.w + btv.w;
        ((float4*)out)[gw * 32 + lane] = o;
    }
}

// ---------------- launch ----------------
extern "C" void kernel_launch(void* const* d_in, const int* in_sizes, int n_in,
                              void* d_out, int out_size) {
    const float* x   = (const float*)d_in[0];
    const void*  ei  = d_in[1];
    const float* W1  = (const float*)d_in[2];
    const float* b1  = (const float*)d_in[3];
    const float* W2  = (const float*)d_in[4];
    const float* b2  = (const float*)d_in[5];
    const float* gm  = (const float*)d_in[6];
    const float* bt  = (const float*)d_in[7];
    float*       out = (float*)d_out;

    int E = in_sizes[1] / 2;

    __half* hbuf; cudaGetSymbolAddress((void**)&hbuf, g_h);
    float*  bufA; cudaGetSymbolAddress((void**)&bufA, g_bufA);

    const size_t smem_gemm = (128 * 128 + 64 * 128) * sizeof(float);  // 96 KB
    cudaFuncSetAttribute(k_gemm<false>, cudaFuncAttributeMaxDynamicSharedMemorySize,
                         (int)smem_gemm);
    cudaFuncSetAttribute(k_gemm<true>, cudaFuncAttributeMaxDynamicSharedMemorySize,
                         (int)smem_gemm);

    int ebl = (E + 255) / 256;
    int nbl = (NN + 255) / 256;
    int agg_blocks = (NN * 32 + 255) / 256;
    int gemm_blocks = (NN + 63) / 64;

    // ---- CSR build (shared by both layers) ----
    k_detect<<<1, 1>>>((const int*)ei);
    k_zero<<<nbl, 256>>>();
    k_count<<<ebl, 256>>>(ei, E);
    k_dinv<<<nbl, 256>>>();
    k_scan<<<1, 1024>>>(NN);
    k_scatter<<<ebl, 256>>>(ei, E);

    // ---- layer 1: g1 = x@W1 (fp16) ; a1 = relu(agg(g1)+b1) (fp32) ----
    k_gemm<false><<<gemm_blocks, 256, smem_gemm>>>(x, W1, hbuf, NN);
    k_agg<0><<<agg_blocks, 256>>>((const uint2*)hbuf, bufA, b1, nullptr, nullptr);

    // ---- layer 2: g2 = a1@W2 (fp16) ; out = LN(agg(g2)+b2) ----
    k_gemm<false><<<gemm_blocks, 256, smem_gemm>>>(bufA, W2, hbuf, NN);
    k_agg<1><<<agg_blocks, 256>>>((const uint2*)hbuf, out, b2, gm, bt);
}

// round 4
// speedup vs baseline: 1.7612x; 1.3142x over previous
#include <cuda_runtime.h>
#include <cuda_fp16.h>
#include <cuda_bf16.h>
#include <cstdint>

// Problem constants
#define NN 100000
#define EE 1600000
#define DD 128

// ---------------- device scratch (no allocations allowed) ----------------
__device__ int    g_is64;
__device__ int    g_deg[NN];
__device__ int    g_rowptr[NN + 1];
__device__ int    g_cursor[NN];
__device__ int2   g_edge[EE];        // (col, wgt-as-int-bits)
__device__ float  g_dinv[NN];
__device__ __half g_h[NN * DD];      // GEMM output (h1, then h2)
__device__ __half g_a1[NN * DD];     // layer-1 activation (fp16)

// ---------------- helpers ----------------
__device__ __forceinline__ int load_idx(const void* ei, int pos, int is64) {
    if (is64) return (int)((const long long*)ei)[pos];
    return ((const int*)ei)[pos];
}

// ---------------- graph-build kernels ----------------

// Detect int64 vs int32 edge_index: int64 node ids (<2^31) have zero hi-words
// at every odd int32 position.
__global__ void k_detect(const int* __restrict__ ei32) {
    int zeros = 0;
#pragma unroll
    for (int i = 0; i < 64; i++)
        if (ei32[2 * i + 1] == 0) zeros++;
    g_is64 = (zeros >= 60) ? 1 : 0;
}

__global__ void k_zero() {
    int i = blockIdx.x * blockDim.x + threadIdx.x;
    if (i < NN) { g_deg[i] = 0; g_cursor[i] = 0; }
}

__global__ void k_count(const void* __restrict__ ei, int E) {
    int i = blockIdx.x * blockDim.x + threadIdx.x;
    if (i >= E) return;
    int d = load_idx(ei, E + i, g_is64);
    if ((unsigned)d < (unsigned)NN) atomicAdd(&g_deg[d], 1);
}

__global__ void k_dinv() {
    int i = blockIdx.x * blockDim.x + threadIdx.x;
    if (i < NN) g_dinv[i] = rsqrtf((float)g_deg[i] + 1.0f);
}

// Single-block scan via warp shuffles: g_rowptr[i+1] = sum(deg[0..i]).
__global__ void k_scan(int n) {
    __shared__ int wsum[32];
    __shared__ int carry;
    int t = threadIdx.x, lane = t & 31, w = t >> 5;
    if (t == 0) { carry = 0; g_rowptr[0] = 0; }
    __syncthreads();
    for (int base = 0; base < n; base += 1024) {
        int v = (base + t < n) ? g_deg[base + t] : 0;
        int s = v;
#pragma unroll
        for (int off = 1; off < 32; off <<= 1) {
            int u = __shfl_up_sync(0xFFFFFFFFu, s, off);
            if (lane >= off) s += u;
        }
        if (lane == 31) wsum[w] = s;
        __syncthreads();
        if (w == 0) {
            int ws = wsum[lane];
#pragma unroll
            for (int off = 1; off < 32; off <<= 1) {
                int u = __shfl_up_sync(0xFFFFFFFFu, ws, off);
                if (lane >= off) ws += u;
            }
            wsum[lane] = ws;
        }
        __syncthreads();
        int c = carry;
        int pre = (w > 0) ? wsum[w - 1] : 0;
        if (base + t < n) g_rowptr[base + t + 1] = c + pre + s;
        __syncthreads();
        if (t == 0) carry = c + wsum[31];
        __syncthreads();
    }
}

__global__ void k_scatter(const void* __restrict__ ei, int E) {
    int i = blockIdx.x * blockDim.x + threadIdx.x;
    if (i >= E) return;
    int is64 = g_is64;
    int s = load_idx(ei, i, is64);
    int d = load_idx(ei, E + i, is64);
    if ((unsigned)s >= (unsigned)NN || (unsigned)d >= (unsigned)NN) return;
    int pos = atomicAdd(&g_cursor[d], 1);
    int idx = g_rowptr[d] + pos;
    float w = g_dinv[s] * g_dinv[d];
    g_edge[idx] = make_int2(s, __float_as_int(w));
}

// ---------------- tensor-core GEMM ----------------
// out[n,128] (fp16) = A[n,128] @ W[128,128], fp32 accumulation via
// mma.sync.m16n8k16. Block: 256 threads (8 warps), 128-row tile.
// Warp w computes rows [16w, 16w+16) x all 128 cols.
// smem: sA[128][136] half (row-major), sBT[128][136] half (W transposed: [n][k]).
#define SRS 136  // smem row stride in halves

template <bool HALF_IN>
__global__ void k_gemm_tc(const void* __restrict__ Ain, const float* __restrict__ Wm,
                          __half* __restrict__ out, int n) {
    extern __shared__ __half smh[];
    __half* sA = smh;               // 128*SRS
    __half* sBT = smh + 128 * SRS;  // 128*SRS
    int tid = threadIdx.x;
    int row0 = blockIdx.x * 128;

    // Stage W^T as fp16: W row-major [k][n] -> sBT[n][k]
#pragma unroll
    for (int i = 0; i < 64; i++) {
        int idx = tid + 256 * i;        // idx = k*128 + n
        int k = idx >> 7, nn = idx & 127;
        sBT[nn * SRS + k] = __float2half(Wm[idx]);
    }

    // Stage A tile (128 rows x 128 cols) as fp16
    if (!HALF_IN) {
        const float4* A4 = (const float4*)Ain;
#pragma unroll
        for (int i = 0; i < 16; i++) {
            int idx = tid + 256 * i;     // float4 index in tile
            int r = idx >> 5, c = (idx & 31) * 4;
            float4 v = make_float4(0.f, 0.f, 0.f, 0.f);
            if (row0 + r < n) v = A4[(row0 + r) * 32 + (idx & 31)];
            __half2 h0 = __floats2half2_rn(v.x, v.y);
            __half2 h1 = __floats2half2_rn(v.z, v.w);
            *(__half2*)(sA + r * SRS + c) = h0;
            *(__half2*)(sA + r * SRS + c + 2) = h1;
        }
    } else {
        const uint2* A2 = (const uint2*)Ain;
#pragma unroll
        for (int i = 0; i < 16; i++) {
            int idx = tid + 256 * i;
            int r = idx >> 5, c = (idx & 31) * 4;
            uint2 u = make_uint2(0u, 0u);
            if (row0 + r < n) u = A2[(row0 + r) * 32 + (idx & 31)];
            *(uint32_t*)(sA + r * SRS + c) = u.x;
            *(uint32_t*)(sA + r * SRS + c + 2) = u.y;
        }
    }
    __syncthreads();

    int lane = tid & 31, warp = tid >> 5;
    int g = lane >> 2, tg = lane & 3;
    int rb = warp * 16;

    float acc[16][4];
#pragma unroll
    for (int nt = 0; nt < 16; nt++)
#pragma unroll
        for (int q = 0; q < 4; q++) acc[nt][q] = 0.f;

#pragma unroll
    for (int ks = 0; ks < 8; ks++) {
        int k0 = ks * 16;
        uint32_t a0 = *(const uint32_t*)(sA + (rb + g) * SRS + k0 + tg * 2);
        uint32_t a1 = *(const uint32_t*)(sA + (rb + g + 8) * SRS + k0 + tg * 2);
        uint32_t a2 = *(const uint32_t*)(sA + (rb + g) * SRS + k0 + 8 + tg * 2);
        uint32_t a3 = *(const uint32_t*)(sA + (rb + g + 8) * SRS + k0 + 8 + tg * 2);
#pragma unroll
        for (int nt = 0; nt < 16; nt++) {
            uint32_t b0 = *(const uint32_t*)(sBT + (nt * 8 + g) * SRS + k0 + tg * 2);
            uint32_t b1 = *(const uint32_t*)(sBT + (nt * 8 + g) * SRS + k0 + 8 + tg * 2);
            asm volatile(
                "mma.sync.aligned.m16n8k16.row.col.f32.f16.f16.f32 "
                "{%0,%1,%2,%3},{%4,%5,%6,%7},{%8,%9},{%0,%1,%2,%3};"
                : "+f"(acc[nt][0]), "+f"(acc[nt][1]),
                  "+f"(acc[nt][2]), "+f"(acc[nt][3])
                : "r"(a0), "r"(a1), "r"(a2), "r"(a3), "r"(b0), "r"(b1));
        }
    }

    // Epilogue: fp16 stores. c0,c1 -> (row rb+g, col tg*2); c2,c3 -> row+8.
    int r1 = row0 + rb + g;
    int r2 = r1 + 8;
#pragma unroll
    for (int nt = 0; nt < 16; nt++) {
        int c = nt * 8 + tg * 2;
        if (r1 < n) {
            __half2 h = __floats2half2_rn(acc[nt][0], acc[nt][1]);
            *(__half2*)(out + r1 * 128 + c) = h;
        }
        if (r2 < n) {
            __half2 h = __floats2half2_rn(acc[nt][2], acc[nt][3]);
            *(__half2*)(out + r2 * 128 + c) = h;
        }
    }
}

// ---------------- aggregation over fp16 rows ----------------
// row(i) = sum_j w_j * h[col_j] + dinv_i^2 * h[i] + bias, then ReLU (fp16 out)
// or LayerNorm (fp32 out). Warp per node, lane owns 4 features.
template <int MODE>
__global__ void k_agg(const uint2* __restrict__ hin, void* __restrict__ outp,
                      const float* __restrict__ bias, const float* __restrict__ gamma,
                      const float* __restrict__ beta) {
    int gw = (blockIdx.x * blockDim.x + threadIdx.x) >> 5;
    int lane = threadIdx.x & 31;
    if (gw >= NN) return;
    int s = g_rowptr[gw];
    int e = g_rowptr[gw + 1];
    float di = g_dinv[gw];
    float sw = di * di;

    float ax, ay, az, aw;
    {
        uint2 u = hin[gw * 32 + lane];
        __half2 h0 = *reinterpret_cast<__half2*>(&u.x);
        __half2 h1 = *reinterpret_cast<__half2*>(&u.y);
        float2 f0 = __half22float2(h0), f1 = __half22float2(h1);
        ax = f0.x * sw; ay = f0.y * sw; az = f1.x * sw; aw = f1.y * sw;
    }

    int j = s;
    for (; j + 1 < e; j += 2) {
        int2 e0 = g_edge[j], e1 = g_edge[j + 1];
        float w0 = __int_as_float(e0.y), w1 = __int_as_float(e1.y);
        uint2 u0 = hin[e0.x * 32 + lane];
        uint2 u1 = hin[e1.x * 32 + lane];
        __half2 p0 = *reinterpret_cast<__half2*>(&u0.x);
        __half2 p1 = *reinterpret_cast<__half2*>(&u0.y);
        __half2 q0 = *reinterpret_cast<__half2*>(&u1.x);
        __half2 q1 = *reinterpret_cast<__half2*>(&u1.y);
        float2 fp0 = __half22float2(p0), fp1 = __half22float2(p1);
        float2 fq0 = __half22float2(q0), fq1 = __half22float2(q1);
        ax += fp0.x * w0 + fq0.x * w1;
        ay += fp0.y * w0 + fq0.y * w1;
        az += fp1.x * w0 + fq1.x * w1;
        aw += fp1.y * w0 + fq1.y * w1;
    }
    if (j < e) {
        int2 e0 = g_edge[j];
        float w0 = __int_as_float(e0.y);
        uint2 u0 = hin[e0.x * 32 + lane];
        __half2 p0 = *reinterpret_cast<__half2*>(&u0.x);
        __half2 p1 = *reinterpret_cast<__half2*>(&u0.y);
        float2 fp0 = __half22float2(p0), fp1 = __half22float2(p1);
        ax += fp0.x * w0;
        ay += fp0.y * w0;
        az += fp1.x * w0;
        aw += fp1.y * w0;
    }

    float4 bv = ((const float4*)bias)[lane];
    ax += bv.x; ay += bv.y; az += bv.z; aw += bv.w;

    if (MODE == 0) {
        __half2 h0 = __floats2half2_rn(fmaxf(ax, 0.f), fmaxf(ay, 0.f));
        __half2 h1 = __floats2half2_rn(fmaxf(az, 0.f), fmaxf(aw, 0.f));
        uint2 u;
        u.x = *reinterpret_cast<unsigned*>(&h0);
        u.y = *reinterpret_cast<unsigned*>(&h1);
        ((uint2*)outp)[gw * 32 + lane] = u;
    } else {
        float sum = ax + ay + az + aw;
#pragma unroll
        for (int off = 16; off > 0; off >>= 1)
            sum += __shfl_xor_sync(0xFFFFFFFFu, sum, off);
        float mu = sum * (1.0f / 128.0f);
        float dx = ax - mu, dy = ay - mu, dz = az - mu, dw = aw - mu;
        float sq = dx * dx + dy * dy + dz * dz + dw * dw;
#pragma unroll
        for (int off = 16; off > 0; off >>= 1)
            sq += __shfl_xor_sync(0xFFFFFFFFu, sq, off);
        float rstd = rsqrtf(sq * (1.0f / 128.0f) + 1e-5f);
        float4 gv = ((const float4*)gamma)[lane];
        float4 btv = ((const float4*)beta)[lane];
        float4 o;
        o.x = dx * rstd * gv.x + btv.x;
        o.y = dy * rstd * gv.y + btv.y;
        o.z = dz * rstd * gv.z + btv.z;
        o.w = dw * rstd * gv.w + btv.w;
        ((float4*)outp)[gw * 32 + lane] = o;
    }
}

// ---------------- launch ----------------
extern "C" void kernel_launch(void* const* d_in, const int* in_sizes, int n_in,
                              void* d_out, int out_size) {
    const float* x   = (const float*)d_in[0];
    const void*  ei  = d_in[1];
    const float* W1  = (const float*)d_in[2];
    const float* b1  = (const float*)d_in[3];
    const float* W2  = (const float*)d_in[4];
    const float* b2  = (const float*)d_in[5];
    const float* gm  = (const float*)d_in[6];
    const float* bt  = (const float*)d_in[7];
    float*       out = (float*)d_out;

    int E = in_sizes[1] / 2;

    __half* hbuf; cudaGetSymbolAddress((void**)&hbuf, g_h);
    __half* a1buf; cudaGetSymbolAddress((void**)&a1buf, g_a1);

    const size_t smem_gemm = 2 * 128 * SRS * sizeof(__half);  // 69632 B
    cudaFuncSetAttribute(k_gemm_tc<false>, cudaFuncAttributeMaxDynamicSharedMemorySize,
                         (int)smem_gemm);
    cudaFuncSetAttribute(k_gemm_tc<true>, cudaFuncAttributeMaxDynamicSharedMemorySize,
                         (int)smem_gemm);

    int ebl = (E + 255) / 256;
    int nbl = (NN + 255) / 256;
    int agg_blocks = (NN * 32 + 255) / 256;
    int gemm_blocks = (NN + 127) / 128;

    // ---- CSR build (shared by both layers) ----
    k_detect<<<1, 1>>>((const int*)ei);
    k_zero<<<nbl, 256>>>();
    k_count<<<ebl, 256>>>(ei, E);
    k_dinv<<<nbl, 256>>>();
    k_scan<<<1, 1024>>>(NN);
    k_scatter<<<ebl, 256>>>(ei, E);

    // ---- layer 1: h1 = x@W1 (fp16) ; a1 = relu(agg(h1)+b1) (fp16) ----
    k_gemm_tc<false><<<gemm_blocks, 256, smem_gemm>>>(x, W1, hbuf, NN);
    k_agg<0><<<agg_blocks, 256>>>((const uint2*)hbuf, a1buf, b1, nullptr, nullptr);

    // ---- layer 2: h2 = a1@W2 (fp16) ; out = LN(agg(h2)+b2) (fp32) ----
    k_gemm_tc<true><<<gemm_blocks, 256, smem_gemm>>>(a1buf, W2, hbuf, NN);
    k_agg<1><<<agg_blocks, 256>>>((const uint2*)hbuf, out, b2, gm, bt);
}

// round 5
// speedup vs baseline: 1.8635x; 1.0581x over previous
#include <cuda_runtime.h>
#include <cuda_fp16.h>
#include <cuda_bf16.h>
#include <cstdint>

// Problem constants
#define NN 100000
#define EE 1600000
#define DD 128

// ---------------- device scratch (no allocations allowed) ----------------
__device__ int    g_is64;
__device__ int    g_deg[NN];
__device__ int    g_rowptr[NN + 1];
__device__ int    g_cursor[NN];
__device__ int2   g_edge[EE];        // (col, wgt-as-int-bits)
__device__ float  g_dinv[NN];
__device__ __half g_h[NN * DD];      // GEMM output (h1, then h2)
__device__ __half g_a1[NN * DD];     // layer-1 activation (fp16)

// ---------------- helpers ----------------
__device__ __forceinline__ int load_idx(const void* ei, int pos, int is64) {
    if (is64) return (int)((const long long*)ei)[pos];
    return ((const int*)ei)[pos];
}

// ---------------- graph-build kernels ----------------

// zero counters + dtype detect (int64 node ids < 2^31 have zero hi-words at
// every odd int32 position).
__global__ void k_init(const int* __restrict__ ei32) {
    int i = blockIdx.x * blockDim.x + threadIdx.x;
    if (i < NN) { g_deg[i] = 0; g_cursor[i] = 0; }
    if (i == 0) {
        int zeros = 0;
#pragma unroll
        for (int j = 0; j < 64; j++)
            if (ei32[2 * j + 1] == 0) zeros++;
        g_is64 = (zeros >= 60) ? 1 : 0;
    }
}

__global__ void k_count(const void* __restrict__ ei, int E) {
    int i = blockIdx.x * blockDim.x + threadIdx.x;
    int is64 = g_is64;
    if (!is64 && (E & 3) == 0) {
        // vectorized: 4 dst per thread
        int base = 4 * i;
        if (base >= E) return;
        const int4* dst4 = (const int4*)((const int*)ei + E);
        int4 d = dst4[i];
        if ((unsigned)d.x < (unsigned)NN) atomicAdd(&g_deg[d.x], 1);
        if ((unsigned)d.y < (unsigned)NN) atomicAdd(&g_deg[d.y], 1);
        if ((unsigned)d.z < (unsigned)NN) atomicAdd(&g_deg[d.z], 1);
        if ((unsigned)d.w < (unsigned)NN) atomicAdd(&g_deg[d.w], 1);
    } else {
        if (i >= E) return;
        int d = load_idx(ei, E + i, is64);
        if ((unsigned)d < (unsigned)NN) atomicAdd(&g_deg[d], 1);
    }
}

// Single-block scan via warp shuffles: g_rowptr[i+1] = sum(deg[0..i]).
// Also computes g_dinv (fused).
__global__ void k_scan(int n) {
    __shared__ int wsum[32];
    __shared__ int carry;
    int t = threadIdx.x, lane = t & 31, w = t >> 5;
    if (t == 0) { carry = 0; g_rowptr[0] = 0; }
    __syncthreads();
    for (int base = 0; base < n; base += 1024) {
        int v = (base + t < n) ? g_deg[base + t] : 0;
        if (base + t < n) g_dinv[base + t] = rsqrtf((float)v + 1.0f);
        int s = v;
#pragma unroll
        for (int off = 1; off < 32; off <<= 1) {
            int u = __shfl_up_sync(0xFFFFFFFFu, s, off);
            if (lane >= off) s += u;
        }
        if (lane == 31) wsum[w] = s;
        __syncthreads();
        if (w == 0) {
            int ws = wsum[lane];
#pragma unroll
            for (int off = 1; off < 32; off <<= 1) {
                int u = __shfl_up_sync(0xFFFFFFFFu, ws, off);
                if (lane >= off) ws += u;
            }
            wsum[lane] = ws;
        }
        __syncthreads();
        int c = carry;
        int pre = (w > 0) ? wsum[w - 1] : 0;
        if (base + t < n) g_rowptr[base + t + 1] = c + pre + s;
        __syncthreads();
        if (t == 0) carry = c + wsum[31];
        __syncthreads();
    }
}

__device__ __forceinline__ void scatter_one(int s, int d) {
    if ((unsigned)s >= (unsigned)NN || (unsigned)d >= (unsigned)NN) return;
    int pos = atomicAdd(&g_cursor[d], 1);
    int idx = g_rowptr[d] + pos;
    float w = g_dinv[s] * g_dinv[d];
    g_edge[idx] = make_int2(s, __float_as_int(w));
}

__global__ void k_scatter(const void* __restrict__ ei, int E) {
    int i = blockIdx.x * blockDim.x + threadIdx.x;
    int is64 = g_is64;
    if (!is64 && (E & 3) == 0) {
        int base = 4 * i;
        if (base >= E) return;
        const int4* src4 = (const int4*)((const int*)ei);
        const int4* dst4 = (const int4*)((const int*)ei + E);
        int4 s = src4[i];
        int4 d = dst4[i];
        scatter_one(s.x, d.x);
        scatter_one(s.y, d.y);
        scatter_one(s.z, d.z);
        scatter_one(s.w, d.w);
    } else {
        if (i >= E) return;
        int s = load_idx(ei, i, is64);
        int d = load_idx(ei, E + i, is64);
        scatter_one(s, d);
    }
}

// ---------------- tensor-core GEMM ----------------
// out[n,128] (fp16) = A[n,128] @ W[128,128], fp32 accumulation via
// mma.sync.m16n8k16. Block: 256 threads (8 warps), 128-row tile.
#define SRS 136  // smem row stride in halves

template <bool HALF_IN>
__global__ void k_gemm_tc(const void* __restrict__ Ain, const float* __restrict__ Wm,
                          __half* __restrict__ out, int n) {
    extern __shared__ __half smh[];
    __half* sA = smh;               // 128*SRS
    __half* sBT = smh + 128 * SRS;  // 128*SRS
    int tid = threadIdx.x;
    int row0 = blockIdx.x * 128;

    // Stage W^T as fp16: W row-major [k][n] -> sBT[n][k]
#pragma unroll
    for (int i = 0; i < 64; i++) {
        int idx = tid + 256 * i;        // idx = k*128 + n
        int k = idx >> 7, nn = idx & 127;
        sBT[nn * SRS + k] = __float2half(Wm[idx]);
    }

    // Stage A tile (128 rows x 128 cols) as fp16
    if (!HALF_IN) {
        const float4* A4 = (const float4*)Ain;
#pragma unroll
        for (int i = 0; i < 16; i++) {
            int idx = tid + 256 * i;
            int r = idx >> 5, c = (idx & 31) * 4;
            float4 v = make_float4(0.f, 0.f, 0.f, 0.f);
            if (row0 + r < n) v = A4[(row0 + r) * 32 + (idx & 31)];
            __half2 h0 = __floats2half2_rn(v.x, v.y);
            __half2 h1 = __floats2half2_rn(v.z, v.w);
            *(__half2*)(sA + r * SRS + c) = h0;
            *(__half2*)(sA + r * SRS + c + 2) = h1;
        }
    } else {
        const uint2* A2 = (const uint2*)Ain;
#pragma unroll
        for (int i = 0; i < 16; i++) {
            int idx = tid + 256 * i;
            int r = idx >> 5, c = (idx & 31) * 4;
            uint2 u = make_uint2(0u, 0u);
            if (row0 + r < n) u = A2[(row0 + r) * 32 + (idx & 31)];
            *(uint32_t*)(sA + r * SRS + c) = u.x;
            *(uint32_t*)(sA + r * SRS + c + 2) = u.y;
        }
    }
    __syncthreads();

    int lane = tid & 31, warp = tid >> 5;
    int g = lane >> 2, tg = lane & 3;
    int rb = warp * 16;

    float acc[16][4];
#pragma unroll
    for (int nt = 0; nt < 16; nt++)
#pragma unroll
        for (int q = 0; q < 4; q++) acc[nt][q] = 0.f;

#pragma unroll
    for (int ks = 0; ks < 8; ks++) {
        int k0 = ks * 16;
        uint32_t a0 = *(const uint32_t*)(sA + (rb + g) * SRS + k0 + tg * 2);
        uint32_t a1 = *(const uint32_t*)(sA + (rb + g + 8) * SRS + k0 + tg * 2);
        uint32_t a2 = *(const uint32_t*)(sA + (rb + g) * SRS + k0 + 8 + tg * 2);
        uint32_t a3 = *(const uint32_t*)(sA + (rb + g + 8) * SRS + k0 + 8 + tg * 2);
#pragma unroll
        for (int nt = 0; nt < 16; nt++) {
            uint32_t b0 = *(const uint32_t*)(sBT + (nt * 8 + g) * SRS + k0 + tg * 2);
            uint32_t b1 = *(const uint32_t*)(sBT + (nt * 8 + g) * SRS + k0 + 8 + tg * 2);
            asm volatile(
                "mma.sync.aligned.m16n8k16.row.col.f32.f16.f16.f32 "
                "{%0,%1,%2,%3},{%4,%5,%6,%7},{%8,%9},{%0,%1,%2,%3};"
                : "+f"(acc[nt][0]), "+f"(acc[nt][1]),
                  "+f"(acc[nt][2]), "+f"(acc[nt][3])
                : "r"(a0), "r"(a1), "r"(a2), "r"(a3), "r"(b0), "r"(b1));
        }
    }

    int r1 = row0 + rb + g;
    int r2 = r1 + 8;
#pragma unroll
    for (int nt = 0; nt < 16; nt++) {
        int c = nt * 8 + tg * 2;
        if (r1 < n) {
            __half2 h = __floats2half2_rn(acc[nt][0], acc[nt][1]);
            *(__half2*)(out + r1 * 128 + c) = h;
        }
        if (r2 < n) {
            __half2 h = __floats2half2_rn(acc[nt][2], acc[nt][3]);
            *(__half2*)(out + r2 * 128 + c) = h;
        }
    }
}

// ---------------- aggregation over fp16 rows ----------------
// row(i) = sum_j w_j * h[col_j] + dinv_i^2 * h[i] + bias, then ReLU (fp16 out)
// or LayerNorm (fp32 out). Warp per node, lane owns 4 features. Unroll 4.
template <int MODE>
__global__ void k_agg(const uint2* __restrict__ hin, void* __restrict__ outp,
                      const float* __restrict__ bias, const float* __restrict__ gamma,
                      const float* __restrict__ beta) {
    int gw = (blockIdx.x * blockDim.x + threadIdx.x) >> 5;
    int lane = threadIdx.x & 31;
    if (gw >= NN) return;
    int s = g_rowptr[gw];
    int e = g_rowptr[gw + 1];
    float di = g_dinv[gw];
    float sw = di * di;

    float ax, ay, az, aw;
    {
        uint2 u = hin[gw * 32 + lane];
        __half2 h0 = *reinterpret_cast<__half2*>(&u.x);
        __half2 h1 = *reinterpret_cast<__half2*>(&u.y);
        float2 f0 = __half22float2(h0), f1 = __half22float2(h1);
        ax = f0.x * sw; ay = f0.y * sw; az = f1.x * sw; aw = f1.y * sw;
    }

    int j = s;
    for (; j + 3 < e; j += 4) {
        int2 e0 = g_edge[j],     e1 = g_edge[j + 1];
        int2 e2 = g_edge[j + 2], e3 = g_edge[j + 3];
        uint2 u0 = hin[e0.x * 32 + lane];
        uint2 u1 = hin[e1.x * 32 + lane];
        uint2 u2 = hin[e2.x * 32 + lane];
        uint2 u3 = hin[e3.x * 32 + lane];
        float w0 = __int_as_float(e0.y), w1 = __int_as_float(e1.y);
        float w2 = __int_as_float(e2.y), w3 = __int_as_float(e3.y);
        float2 p0 = __half22float2(*reinterpret_cast<__half2*>(&u0.x));
        float2 p1 = __half22float2(*reinterpret_cast<__half2*>(&u0.y));
        float2 q0 = __half22float2(*reinterpret_cast<__half2*>(&u1.x));
        float2 q1 = __half22float2(*reinterpret_cast<__half2*>(&u1.y));
        float2 r0 = __half22float2(*reinterpret_cast<__half2*>(&u2.x));
        float2 r1 = __half22float2(*reinterpret_cast<__half2*>(&u2.y));
        float2 t0 = __half22float2(*reinterpret_cast<__half2*>(&u3.x));
        float2 t1 = __half22float2(*reinterpret_cast<__half2*>(&u3.y));
        ax += p0.x * w0 + q0.x * w1 + r0.x * w2 + t0.x * w3;
        ay += p0.y * w0 + q0.y * w1 + r0.y * w2 + t0.y * w3;
        az += p1.x * w0 + q1.x * w1 + r1.x * w2 + t1.x * w3;
        aw += p1.y * w0 + q1.y * w1 + r1.y * w2 + t1.y * w3;
    }
    for (; j < e; j++) {
        int2 e0 = g_edge[j];
        float w0 = __int_as_float(e0.y);
        uint2 u0 = hin[e0.x * 32 + lane];
        float2 p0 = __half22float2(*reinterpret_cast<__half2*>(&u0.x));
        float2 p1 = __half22float2(*reinterpret_cast<__half2*>(&u0.y));
        ax += p0.x * w0;
        ay += p0.y * w0;
        az += p1.x * w0;
        aw += p1.y * w0;
    }

    float4 bv = ((const float4*)bias)[lane];
    ax += bv.x; ay += bv.y; az += bv.z; aw += bv.w;

    if (MODE == 0) {
        __half2 h0 = __floats2half2_rn(fmaxf(ax, 0.f), fmaxf(ay, 0.f));
        __half2 h1 = __floats2half2_rn(fmaxf(az, 0.f), fmaxf(aw, 0.f));
        uint2 u;
        u.x = *reinterpret_cast<unsigned*>(&h0);
        u.y = *reinterpret_cast<unsigned*>(&h1);
        ((uint2*)outp)[gw * 32 + lane] = u;
    } else {
        float sum = ax + ay + az + aw;
#pragma unroll
        for (int off = 16; off > 0; off >>= 1)
            sum += __shfl_xor_sync(0xFFFFFFFFu, sum, off);
        float mu = sum * (1.0f / 128.0f);
        float dx = ax - mu, dy = ay - mu, dz = az - mu, dw = aw - mu;
        float sq = dx * dx + dy * dy + dz * dz + dw * dw;
#pragma unroll
        for (int off = 16; off > 0; off >>= 1)
            sq += __shfl_xor_sync(0xFFFFFFFFu, sq, off);
        float rstd = rsqrtf(sq * (1.0f / 128.0f) + 1e-5f);
        float4 gv = ((const float4*)gamma)[lane];
        float4 btv = ((const float4*)beta)[lane];
        float4 o;
        o.x = dx * rstd * gv.x + btv.x;
        o.y = dy * rstd * gv.y + btv.y;
        o.z = dz * rstd * gv.z + btv.z;
        o.w = dw * rstd * gv.w + btv.w;
        ((float4*)outp)[gw * 32 + lane] = o;
    }
}

// ---------------- launch ----------------
extern "C" void kernel_launch(void* const* d_in, const int* in_sizes, int n_in,
                              void* d_out, int out_size) {
    const float* x   = (const float*)d_in[0];
    const void*  ei  = d_in[1];
    const float* W1  = (const float*)d_in[2];
    const float* b1  = (const float*)d_in[3];
    const float* W2  = (const float*)d_in[4];
    const float* b2  = (const float*)d_in[5];
    const float* gm  = (const float*)d_in[6];
    const float* bt  = (const float*)d_in[7];
    float*       out = (float*)d_out;

    int E = in_sizes[1] / 2;

    __half* hbuf; cudaGetSymbolAddress((void**)&hbuf, g_h);
    __half* a1buf; cudaGetSymbolAddress((void**)&a1buf, g_a1);

    const size_t smem_gemm = 2 * 128 * SRS * sizeof(__half);  // 69632 B
    static bool s_attr_done = false;
    static cudaStream_t s_side = nullptr;
    static cudaEvent_t ev_fork = nullptr, ev_join = nullptr;
    if (!s_attr_done) {
        cudaFuncSetAttribute(k_gemm_tc<false>,
                             cudaFuncAttributeMaxDynamicSharedMemorySize, (int)smem_gemm);
        cudaFuncSetAttribute(k_gemm_tc<true>,
                             cudaFuncAttributeMaxDynamicSharedMemorySize, (int)smem_gemm);
        cudaStreamCreateWithFlags(&s_side, cudaStreamNonBlocking);
        cudaEventCreateWithFlags(&ev_fork, cudaEventDisableTiming);
        cudaEventCreateWithFlags(&ev_join, cudaEventDisableTiming);
        s_attr_done = true;
    }

    int ebl4 = (E / 4 + 255) / 256;        // vector path block count
    int ebl = (E + 255) / 256;
    int cnt_blocks = ((E & 3) == 0) ? ebl4 : ebl;   // kernel handles both paths
    int nbl = (NN + 255) / 256;
    int agg_blocks = (NN * 32 + 255) / 256;
    int gemm_blocks = (NN + 127) / 128;

    // ---- init (zero + dtype detect) ----
    k_init<<<nbl, 256>>>((const int*)ei);

    // ---- fork: gemm1 = x@W1 on side stream (graph-independent) ----
    cudaEventRecord(ev_fork, 0);
    cudaStreamWaitEvent(s_side, ev_fork, 0);
    k_gemm_tc<false><<<gemm_blocks, 256, smem_gemm, s_side>>>(x, W1, hbuf, NN);
    cudaEventRecord(ev_join, s_side);

    // ---- CSR build on main stream ----
    k_count<<<cnt_blocks, 256>>>(ei, E);
    k_scan<<<1, 1024>>>(NN);
    k_scatter<<<cnt_blocks, 256>>>(ei, E);

    // ---- join, then layer 1 aggregation ----
    cudaStreamWaitEvent(0, ev_join, 0);
    k_agg<0><<<agg_blocks, 256>>>((const uint2*)hbuf, a1buf, b1, nullptr, nullptr);

    // ---- layer 2 ----
    k_gemm_tc<true><<<gemm_blocks, 256, smem_gemm>>>(a1buf, W2, hbuf, NN);
    k_agg<1><<<agg_blocks, 256>>>((const uint2*)hbuf, out, b2, gm, bt);
}

// round 6
// speedup vs baseline: 2.4463x; 1.3127x over previous
#include <cuda_runtime.h>
#include <cuda_fp16.h>
#include <cuda_bf16.h>
#include <cstdint>

// Problem constants
#define NN 100000
#define EE 1600000
#define DD 128
#define NB_SCAN ((NN + 255) / 256)   // 391 scan blocks

// ---------------- device scratch (no allocations allowed) ----------------
__device__ int    g_is64;
__device__ int    g_deg[NN];
__device__ int    g_rowptr[NN + 1];
__device__ int    g_cursor[NN];
__device__ int    g_psum[NB_SCAN];
__device__ int2   g_edge[EE];        // (col, wgt-as-int-bits)
__device__ float  g_dinv[NN];
__device__ __half g_h[NN * DD];      // GEMM output (h1, then h2)
__device__ __half g_a1[NN * DD];     // layer-1 activation (fp16)

// ---------------- helpers ----------------
__device__ __forceinline__ int load_idx(const void* ei, int pos, int is64) {
    if (is64) return (int)((const long long*)ei)[pos];
    return ((const int*)ei)[pos];
}

// ---------------- graph-build kernels ----------------

// zero counters + dtype detect (int64 node ids < 2^31 have zero hi-words at
// every odd int32 position).
__global__ void k_init(const int* __restrict__ ei32) {
    int i = blockIdx.x * blockDim.x + threadIdx.x;
    if (i < NN) { g_deg[i] = 0; g_cursor[i] = 0; }
    if (i == 0) {
        int zeros = 0;
#pragma unroll
        for (int j = 0; j < 64; j++)
            if (ei32[2 * j + 1] == 0) zeros++;
        g_is64 = (zeros >= 60) ? 1 : 0;
    }
}

__global__ void k_count(const void* __restrict__ ei, int E) {
    int i = blockIdx.x * blockDim.x + threadIdx.x;
    int is64 = g_is64;
    if (!is64 && (E & 3) == 0) {
        int base = 4 * i;
        if (base >= E) return;
        const int4* dst4 = (const int4*)((const int*)ei + E);
        int4 d = dst4[i];
        if ((unsigned)d.x < (unsigned)NN) atomicAdd(&g_deg[d.x], 1);
        if ((unsigned)d.y < (unsigned)NN) atomicAdd(&g_deg[d.y], 1);
        if ((unsigned)d.z < (unsigned)NN) atomicAdd(&g_deg[d.z], 1);
        if ((unsigned)d.w < (unsigned)NN) atomicAdd(&g_deg[d.w], 1);
    } else {
        if (i >= E) return;
        int d = load_idx(ei, E + i, is64);
        if ((unsigned)d < (unsigned)NN) atomicAdd(&g_deg[d], 1);
    }
}

// ---- 3-phase parallel scan ----

// Phase 1: per-block (256-element) sums of deg -> g_psum[b]
__global__ void k_reduce() {
    __shared__ int ws[8];
    int b = blockIdx.x, t = threadIdx.x;
    int lane = t & 31, w = t >> 5;
    int i = b * 256 + t;
    int v = (i < NN) ? g_deg[i] : 0;
#pragma unroll
    for (int off = 16; off > 0; off >>= 1)
        v += __shfl_xor_sync(0xFFFFFFFFu, v, off);
    if (lane == 0) ws[w] = v;
    __syncthreads();
    if (t == 0) {
        int s = 0;
#pragma unroll
        for (int k = 0; k < 8; k++) s += ws[k];
        g_psum[b] = s;
    }
}

// Phase 2: exclusive scan of g_psum (NB_SCAN=391 values), one block of 512.
__global__ void k_scan_psum() {
    __shared__ int wsum[16];
    int t = threadIdx.x, lane = t & 31, w = t >> 5;
    int v = (t < NB_SCAN) ? g_psum[t] : 0;
    int s = v;
#pragma unroll
    for (int off = 1; off < 32; off <<= 1) {
        int u = __shfl_up_sync(0xFFFFFFFFu, s, off);
        if (lane >= off) s += u;
    }
    if (lane == 31) wsum[w] = s;
    __syncthreads();
    if (w == 0 && lane < 16) {
        int ws = wsum[lane];
#pragma unroll
        for (int off = 1; off < 16; off <<= 1) {
            int u = __shfl_up_sync(0xFFFFu, ws, off);
            if (lane >= off) ws += u;
        }
        wsum[lane] = ws;
    }
    __syncthreads();
    int pre = (w > 0) ? wsum[w - 1] : 0;
    if (t < NB_SCAN) g_psum[t] = pre + s - v;   // exclusive
}

// Phase 3: block-local inclusive scan + offset -> rowptr; dinv fused.
__global__ void k_scan_final() {
    __shared__ int wsum[8];
    int b = blockIdx.x, t = threadIdx.x;
    int lane = t & 31, w = t >> 5;
    int i = b * 256 + t;
    int v = (i < NN) ? g_deg[i] : 0;
    if (i < NN) g_dinv[i] = rsqrtf((float)v + 1.0f);
    int s = v;
#pragma unroll
    for (int off = 1; off < 32; off <<= 1) {
        int u = __shfl_up_sync(0xFFFFFFFFu, s, off);
        if (lane >= off) s += u;
    }
    if (lane == 31) wsum[w] = s;
    __syncthreads();
    if (w == 0 && lane < 8) {
        int ws = wsum[lane];
#pragma unroll
        for (int off = 1; off < 8; off <<= 1) {
            int u = __shfl_up_sync(0xFFu, ws, off);
            if (lane >= off) ws += u;
        }
        wsum[lane] = ws;
    }
    __syncthreads();
    int pre = (w > 0) ? wsum[w - 1] : 0;
    int base = g_psum[b];
    if (i < NN) g_rowptr[i + 1] = base + pre + s;
    if (b == 0 && t == 0) g_rowptr[0] = 0;
}

__device__ __forceinline__ void scatter_one(int s, int d) {
    if ((unsigned)s >= (unsigned)NN || (unsigned)d >= (unsigned)NN) return;
    int pos = atomicAdd(&g_cursor[d], 1);
    int idx = g_rowptr[d] + pos;
    float w = g_dinv[s] * g_dinv[d];
    g_edge[idx] = make_int2(s, __float_as_int(w));
}

__global__ void k_scatter(const void* __restrict__ ei, int E) {
    int i = blockIdx.x * blockDim.x + threadIdx.x;
    int is64 = g_is64;
    if (!is64 && (E & 3) == 0) {
        int base = 4 * i;
        if (base >= E) return;
        const int4* src4 = (const int4*)((const int*)ei);
        const int4* dst4 = (const int4*)((const int*)ei + E);
        int4 s = src4[i];
        int4 d = dst4[i];
        scatter_one(s.x, d.x);
        scatter_one(s.y, d.y);
        scatter_one(s.z, d.z);
        scatter_one(s.w, d.w);
    } else {
        if (i >= E) return;
        int s = load_idx(ei, i, is64);
        int d = load_idx(ei, E + i, is64);
        scatter_one(s, d);
    }
}

// ---------------- tensor-core GEMM ----------------
// out[n,128] (fp16) = A[n,128] @ W[128,128], fp32 accumulation via
// mma.sync.m16n8k16. Block: 256 threads (8 warps), 128-row tile.
#define SRS 136  // smem row stride in halves

template <bool HALF_IN>
__global__ void k_gemm_tc(const void* __restrict__ Ain, const float* __restrict__ Wm,
                          __half* __restrict__ out, int n) {
    extern __shared__ __half smh[];
    __half* sA = smh;               // 128*SRS
    __half* sBT = smh + 128 * SRS;  // 128*SRS
    int tid = threadIdx.x;
    int row0 = blockIdx.x * 128;

    // Stage W^T as fp16: W row-major [k][n] -> sBT[n][k]
#pragma unroll
    for (int i = 0; i < 64; i++) {
        int idx = tid + 256 * i;        // idx = k*128 + n
        int k = idx >> 7, nn = idx & 127;
        sBT[nn * SRS + k] = __float2half(Wm[idx]);
    }

    // Stage A tile (128 rows x 128 cols) as fp16
    if (!HALF_IN) {
        const float4* A4 = (const float4*)Ain;
#pragma unroll
        for (int i = 0; i < 16; i++) {
            int idx = tid + 256 * i;
            int r = idx >> 5, c = (idx & 31) * 4;
            float4 v = make_float4(0.f, 0.f, 0.f, 0.f);
            if (row0 + r < n) v = A4[(row0 + r) * 32 + (idx & 31)];
            __half2 h0 = __floats2half2_rn(v.x, v.y);
            __half2 h1 = __floats2half2_rn(v.z, v.w);
            *(__half2*)(sA + r * SRS + c) = h0;
            *(__half2*)(sA + r * SRS + c + 2) = h1;
        }
    } else {
        const uint2* A2 = (const uint2*)Ain;
#pragma unroll
        for (int i = 0; i < 16; i++) {
            int idx = tid + 256 * i;
            int r = idx >> 5, c = (idx & 31) * 4;
            uint2 u = make_uint2(0u, 0u);
            if (row0 + r < n) u = A2[(row0 + r) * 32 + (idx & 31)];
            *(uint32_t*)(sA + r * SRS + c) = u.x;
            *(uint32_t*)(sA + r * SRS + c + 2) = u.y;
        }
    }
    __syncthreads();

    int lane = tid & 31, warp = tid >> 5;
    int g = lane >> 2, tg = lane & 3;
    int rb = warp * 16;

    float acc[16][4];
#pragma unroll
    for (int nt = 0; nt < 16; nt++)
#pragma unroll
        for (int q = 0; q < 4; q++) acc[nt][q] = 0.f;

#pragma unroll
    for (int ks = 0; ks < 8; ks++) {
        int k0 = ks * 16;
        uint32_t a0 = *(const uint32_t*)(sA + (rb + g) * SRS + k0 + tg * 2);
        uint32_t a1 = *(const uint32_t*)(sA + (rb + g + 8) * SRS + k0 + tg * 2);
        uint32_t a2 = *(const uint32_t*)(sA + (rb + g) * SRS + k0 + 8 + tg * 2);
        uint32_t a3 = *(const uint32_t*)(sA + (rb + g + 8) * SRS + k0 + 8 + tg * 2);
#pragma unroll
        for (int nt = 0; nt < 16; nt++) {
            uint32_t b0 = *(const uint32_t*)(sBT + (nt * 8 + g) * SRS + k0 + tg * 2);
            uint32_t b1 = *(const uint32_t*)(sBT + (nt * 8 + g) * SRS + k0 + 8 + tg * 2);
            asm volatile(
                "mma.sync.aligned.m16n8k16.row.col.f32.f16.f16.f32 "
                "{%0,%1,%2,%3},{%4,%5,%6,%7},{%8,%9},{%0,%1,%2,%3};"
                : "+f"(acc[nt][0]), "+f"(acc[nt][1]),
                  "+f"(acc[nt][2]), "+f"(acc[nt][3])
                : "r"(a0), "r"(a1), "r"(a2), "r"(a3), "r"(b0), "r"(b1));
        }
    }

    int r1 = row0 + rb + g;
    int r2 = r1 + 8;
#pragma unroll
    for (int nt = 0; nt < 16; nt++) {
        int c = nt * 8 + tg * 2;
        if (r1 < n) {
            __half2 h = __floats2half2_rn(acc[nt][0], acc[nt][1]);
            *(__half2*)(out + r1 * 128 + c) = h;
        }
        if (r2 < n) {
            __half2 h = __floats2half2_rn(acc[nt][2], acc[nt][3]);
            *(__half2*)(out + r2 * 128 + c) = h;
        }
    }
}

// ---------------- aggregation over fp16 rows ----------------
// row(i) = sum_j w_j * h[col_j] + dinv_i^2 * h[i] + bias, then ReLU (fp16 out)
// or LayerNorm (fp32 out). Warp per node, lane owns 4 features. Unroll 4.
template <int MODE>
__global__ void k_agg(const uint2* __restrict__ hin, void* __restrict__ outp,
                      const float* __restrict__ bias, const float* __restrict__ gamma,
                      const float* __restrict__ beta) {
    int gw = (blockIdx.x * blockDim.x + threadIdx.x) >> 5;
    int lane = threadIdx.x & 31;
    if (gw >= NN) return;
    int s = g_rowptr[gw];
    int e = g_rowptr[gw + 1];
    float di = g_dinv[gw];
    float sw = di * di;

    float ax, ay, az, aw;
    {
        uint2 u = hin[gw * 32 + lane];
        __half2 h0 = *reinterpret_cast<__half2*>(&u.x);
        __half2 h1 = *reinterpret_cast<__half2*>(&u.y);
        float2 f0 = __half22float2(h0), f1 = __half22float2(h1);
        ax = f0.x * sw; ay = f0.y * sw; az = f1.x * sw; aw = f1.y * sw;
    }

    int j = s;
    for (; j + 3 < e; j += 4) {
        int2 e0 = g_edge[j],     e1 = g_edge[j + 1];
        int2 e2 = g_edge[j + 2], e3 = g_edge[j + 3];
        uint2 u0 = hin[e0.x * 32 + lane];
        uint2 u1 = hin[e1.x * 32 + lane];
        uint2 u2 = hin[e2.x * 32 + lane];
        uint2 u3 = hin[e3.x * 32 + lane];
        float w0 = __int_as_float(e0.y), w1 = __int_as_float(e1.y);
        float w2 = __int_as_float(e2.y), w3 = __int_as_float(e3.y);
        float2 p0 = __half22float2(*reinterpret_cast<__half2*>(&u0.x));
        float2 p1 = __half22float2(*reinterpret_cast<__half2*>(&u0.y));
        float2 q0 = __half22float2(*reinterpret_cast<__half2*>(&u1.x));
        float2 q1 = __half22float2(*reinterpret_cast<__half2*>(&u1.y));
        float2 r0 = __half22float2(*reinterpret_cast<__half2*>(&u2.x));
        float2 r1 = __half22float2(*reinterpret_cast<__half2*>(&u2.y));
        float2 t0 = __half22float2(*reinterpret_cast<__half2*>(&u3.x));
        float2 t1 = __half22float2(*reinterpret_cast<__half2*>(&u3.y));
        ax += p0.x * w0 + q0.x * w1 + r0.x * w2 + t0.x * w3;
        ay += p0.y * w0 + q0.y * w1 + r0.y * w2 + t0.y * w3;
        az += p1.x * w0 + q1.x * w1 + r1.x * w2 + t1.x * w3;
        aw += p1.y * w0 + q1.y * w1 + r1.y * w2 + t1.y * w3;
    }
    for (; j < e; j++) {
        int2 e0 = g_edge[j];
        float w0 = __int_as_float(e0.y);
        uint2 u0 = hin[e0.x * 32 + lane];
        float2 p0 = __half22float2(*reinterpret_cast<__half2*>(&u0.x));
        float2 p1 = __half22float2(*reinterpret_cast<__half2*>(&u0.y));
        ax += p0.x * w0;
        ay += p0.y * w0;
        az += p1.x * w0;
        aw += p1.y * w0;
    }

    float4 bv = ((const float4*)bias)[lane];
    ax += bv.x; ay += bv.y; az += bv.z; aw += bv.w;

    if (MODE == 0) {
        __half2 h0 = __floats2half2_rn(fmaxf(ax, 0.f), fmaxf(ay, 0.f));
        __half2 h1 = __floats2half2_rn(fmaxf(az, 0.f), fmaxf(aw, 0.f));
        uint2 u;
        u.x = *reinterpret_cast<unsigned*>(&h0);
        u.y = *reinterpret_cast<unsigned*>(&h1);
        ((uint2*)outp)[gw * 32 + lane] = u;
    } else {
        float sum = ax + ay + az + aw;
#pragma unroll
        for (int off = 16; off > 0; off >>= 1)
            sum += __shfl_xor_sync(0xFFFFFFFFu, sum, off);
        float mu = sum * (1.0f / 128.0f);
        float dx = ax - mu, dy = ay - mu, dz = az - mu, dw = aw - mu;
        float sq = dx * dx + dy * dy + dz * dz + dw * dw;
#pragma unroll
        for (int off = 16; off > 0; off >>= 1)
            sq += __shfl_xor_sync(0xFFFFFFFFu, sq, off);
        float rstd = rsqrtf(sq * (1.0f / 128.0f) + 1e-5f);
        float4 gv = ((const float4*)gamma)[lane];
        float4 btv = ((const float4*)beta)[lane];
        float4 o;
        o.x = dx * rstd * gv.x + btv.x;
        o.y = dy * rstd * gv.y + btv.y;
        o.z = dz * rstd * gv.z + btv.z;
        o.w = dw * rstd * gv.w + btv.w;
        ((float4*)outp)[gw * 32 + lane] = o;
    }
}

// ---------------- launch ----------------
extern "C" void kernel_launch(void* const* d_in, const int* in_sizes, int n_in,
                              void* d_out, int out_size) {
    const float* x   = (const float*)d_in[0];
    const void*  ei  = d_in[1];
    const float* W1  = (const float*)d_in[2];
    const float* b1  = (const float*)d_in[3];
    const float* W2  = (const float*)d_in[4];
    const float* b2  = (const float*)d_in[5];
    const float* gm  = (const float*)d_in[6];
    const float* bt  = (const float*)d_in[7];
    float*       out = (float*)d_out;

    int E = in_sizes[1] / 2;

    __half* hbuf; cudaGetSymbolAddress((void**)&hbuf, g_h);
    __half* a1buf; cudaGetSymbolAddress((void**)&a1buf, g_a1);

    const size_t smem_gemm = 2 * 128 * SRS * sizeof(__half);  // 69632 B
    static bool s_attr_done = false;
    static cudaStream_t s_side = nullptr;
    static cudaEvent_t ev_fork = nullptr, ev_join = nullptr;
    if (!s_attr_done) {
        cudaFuncSetAttribute(k_gemm_tc<false>,
                             cudaFuncAttributeMaxDynamicSharedMemorySize, (int)smem_gemm);
        cudaFuncSetAttribute(k_gemm_tc<true>,
                             cudaFuncAttributeMaxDynamicSharedMemorySize, (int)smem_gemm);
        cudaStreamCreateWithFlags(&s_side, cudaStreamNonBlocking);
        cudaEventCreateWithFlags(&ev_fork, cudaEventDisableTiming);
        cudaEventCreateWithFlags(&ev_join, cudaEventDisableTiming);
        s_attr_done = true;
    }

    int ebl4 = (E / 4 + 255) / 256;
    int ebl = (E + 255) / 256;
    int cnt_blocks = ((E & 3) == 0) ? ebl4 : ebl;
    int nbl = (NN + 255) / 256;
    int agg_blocks = (NN * 32 + 255) / 256;
    int gemm_blocks = (NN + 127) / 128;

    // ---- init (zero + dtype detect) ----
    k_init<<<nbl, 256>>>((const int*)ei);

    // ---- fork: gemm1 = x@W1 on side stream (graph-independent) ----
    cudaEventRecord(ev_fork, 0);
    cudaStreamWaitEvent(s_side, ev_fork, 0);
    k_gemm_tc<false><<<gemm_blocks, 256, smem_gemm, s_side>>>(x, W1, hbuf, NN);
    cudaEventRecord(ev_join, s_side);

    // ---- CSR build on main stream ----
    k_count<<<cnt_blocks, 256>>>(ei, E);
    k_reduce<<<NB_SCAN, 256>>>();
    k_scan_psum<<<1, 512>>>();
    k_scan_final<<<NB_SCAN, 256>>>();
    k_scatter<<<cnt_blocks, 256>>>(ei, E);

    // ---- join, then layer 1 aggregation ----
    cudaStreamWaitEvent(0, ev_join, 0);
    k_agg<0><<<agg_blocks, 256>>>((const uint2*)hbuf, a1buf, b1, nullptr, nullptr);

    // ---- layer 2 ----
    k_gemm_tc<true><<<gemm_blocks, 256, smem_gemm>>>(a1buf, W2, hbuf, NN);
    k_agg<1><<<agg_blocks, 256>>>((const uint2*)hbuf, out, b2, gm, bt);
}